// round 1
// baseline (speedup 1.0000x reference)
#include <cuda_runtime.h>
#include <math.h>
#include <stdint.h>

#define N_NODES 10000
#define IN_DIMS 128
#define EMB 64
#define HID 64
#define NEG_SLOPE 0.2f
#define TILE 128
#define NT 79                 // ceil(N/128)
#define NPAD (NT*TILE)        // 10112
#define MAXEDGE 400000

// ---------------- scratch (no allocations allowed) ----------------
__device__ float    g_h[N_NODES*EMB];
__device__ float    g_hp[N_NODES*HID];
__device__ float    g_asrc[N_NODES];
__device__ float    g_adst[N_NODES];
__device__ unsigned g_mord[N_NODES];
__device__ float    g_denom[N_NODES];
__device__ float    g_eval[MAXEDGE + N_NODES];
__device__ float    g_w[MAXEDGE + N_NODES];
__device__ float    g_emb_acc[N_NODES*HID];
__device__ float    g_embP[NPAD*HID];       // emb + b_gat, zero-padded to tile multiple
__device__ float    g_attr_part[IN_DIMS*EMB];
__device__ float    g_xa2[IN_DIMS*HID];     // (relu(x^T W1 + b1)) W2 + b2

// ---------------- helpers ----------------
__device__ __forceinline__ unsigned f2ord(float f) {
    unsigned b = __float_as_uint(f);
    return (b & 0x80000000u) ? ~b : (b | 0x80000000u);
}
__device__ __forceinline__ float ord2f(unsigned u) {
    unsigned b = (u & 0x80000000u) ? (u & 0x7fffffffu) : ~u;
    return __uint_as_float(b);
}

// ---------------- kernels ----------------
__global__ void k_zero() {
    int i = blockIdx.x * blockDim.x + threadIdx.x;
    int stride = gridDim.x * blockDim.x;
    for (int j = i; j < N_NODES*HID; j += stride) g_emb_acc[j] = 0.f;
    for (int j = i; j < N_NODES; j += stride) { g_mord[j] = 0u; g_denom[j] = 0.f; }
    for (int j = i; j < IN_DIMS*EMB; j += stride) g_attr_part[j] = 0.f;
}

// h = relu(x @ W_stru + b_stru)   [N,128]x[128,64]
__global__ __launch_bounds__(256) void k_stru(const float* __restrict__ x,
                                              const float* __restrict__ W,
                                              const float* __restrict__ b) {
    __shared__ float Ws[IN_DIMS*EMB];   // 32KB
    __shared__ float xs[16*IN_DIMS];    // 8KB
    int t = threadIdx.x;
    for (int i = t; i < IN_DIMS*EMB; i += 256) Ws[i] = W[i];
    int nbase = blockIdx.x * 16;
    for (int i = t; i < 16*IN_DIMS; i += 256) {
        int n = nbase + i / IN_DIMS;
        xs[i] = (n < N_NODES) ? x[(size_t)n*IN_DIMS + (i % IN_DIMS)] : 0.f;
    }
    __syncthreads();
    int nl = t >> 4;
    int e0 = (t & 15) * 4;
    float a0=0.f, a1=0.f, a2=0.f, a3=0.f;
    #pragma unroll 4
    for (int k = 0; k < IN_DIMS; k++) {
        float xv = xs[nl*IN_DIMS + k];
        const float* w = &Ws[k*EMB + e0];
        a0 += xv*w[0]; a1 += xv*w[1]; a2 += xv*w[2]; a3 += xv*w[3];
    }
    int n = nbase + nl;
    if (n < N_NODES) {
        float* o = &g_h[n*EMB + e0];
        o[0] = fmaxf(a0 + b[e0+0], 0.f);
        o[1] = fmaxf(a1 + b[e0+1], 0.f);
        o[2] = fmaxf(a2 + b[e0+2], 0.f);
        o[3] = fmaxf(a3 + b[e0+3], 0.f);
    }
}

// hp = h @ W_gat   [N,64]x[64,64]
__global__ __launch_bounds__(256) void k_gatlin(const float* __restrict__ W) {
    __shared__ float Ws[EMB*HID];   // 16KB
    __shared__ float hs[16*EMB];    // 4KB
    int t = threadIdx.x;
    for (int i = t; i < EMB*HID; i += 256) Ws[i] = W[i];
    int nbase = blockIdx.x * 16;
    for (int i = t; i < 16*EMB; i += 256) {
        int n = nbase + i / EMB;
        hs[i] = (n < N_NODES) ? g_h[n*EMB + (i % EMB)] : 0.f;
    }
    __syncthreads();
    int nl = t >> 4;
    int e0 = (t & 15) * 4;
    float a0=0.f, a1=0.f, a2=0.f, a3=0.f;
    #pragma unroll 8
    for (int k = 0; k < EMB; k++) {
        float xv = hs[nl*EMB + k];
        const float* w = &Ws[k*HID + e0];
        a0 += xv*w[0]; a1 += xv*w[1]; a2 += xv*w[2]; a3 += xv*w[3];
    }
    int n = nbase + nl;
    if (n < N_NODES) {
        float* o = &g_hp[n*HID + e0];
        o[0]=a0; o[1]=a1; o[2]=a2; o[3]=a3;
    }
}

// a_src[n] = hp[n].att_src ; a_dst[n] = hp[n].att_dst  (warp per node)
__global__ void k_att(const float* __restrict__ att_s, const float* __restrict__ att_d) {
    int warp = (blockIdx.x * blockDim.x + threadIdx.x) >> 5;
    int lane = threadIdx.x & 31;
    if (warp >= N_NODES) return;
    float h0 = g_hp[warp*HID + lane];
    float h1 = g_hp[warp*HID + 32 + lane];
    float s = h0*att_s[lane] + h1*att_s[32+lane];
    float d = h0*att_d[lane] + h1*att_d[32+lane];
    #pragma unroll
    for (int o = 16; o; o >>= 1) {
        s += __shfl_xor_sync(0xffffffffu, s, o);
        d += __shfl_xor_sync(0xffffffffu, d, o);
    }
    if (lane == 0) { g_asrc[warp] = s; g_adst[warp] = d; }
}

__global__ void k_emax(const int* __restrict__ ei, int E) {
    int i = blockIdx.x * blockDim.x + threadIdx.x;
    if (i >= E + N_NODES) return;
    int s, d;
    if (i < E) { s = ei[i]; d = ei[E + i]; } else { s = d = i - E; }
    float e = g_asrc[s] + g_adst[d];
    e = (e > 0.f) ? e : NEG_SLOPE * e;
    g_eval[i] = e;
    atomicMax(&g_mord[d], f2ord(e));
}

__global__ void k_eexp(const int* __restrict__ ei, int E) {
    int i = blockIdx.x * blockDim.x + threadIdx.x;
    if (i >= E + N_NODES) return;
    int d = (i < E) ? ei[E + i] : (i - E);
    float m = ord2f(g_mord[d]);
    float w = __expf(g_eval[i] - m);
    g_w[i] = w;
    atomicAdd(&g_denom[d], w);
}

// emb_acc[dst] += hp[src] * (w / denom[dst])   (warp per edge, 2 feats/lane)
__global__ void k_eaggr(const int* __restrict__ ei, int E) {
    int warp = (blockIdx.x * blockDim.x + threadIdx.x) >> 5;
    int lane = threadIdx.x & 31;
    if (warp >= E + N_NODES) return;
    int s, d;
    if (warp < E) { s = ei[warp]; d = ei[E + warp]; } else { s = d = warp - E; }
    float coef = g_w[warp] / g_denom[d];
    atomicAdd(&g_emb_acc[d*HID + lane],      g_hp[s*HID + lane]      * coef);
    atomicAdd(&g_emb_acc[d*HID + 32 + lane], g_hp[s*HID + 32 + lane] * coef);
}

// embP = emb_acc + b_gat  (zero padded rows)
__global__ void k_femb(const float* __restrict__ bg) {
    int i = blockIdx.x * blockDim.x + threadIdx.x;
    if (i >= NPAD*HID) return;
    int n = i >> 6, j = i & 63;
    g_embP[i] = (n < N_NODES) ? (g_emb_acc[i] + bg[j]) : 0.f;
}

// attr_part = x^T @ W_attr1  (split-K: 100 blocks of 100 rows each)
__global__ __launch_bounds__(256) void k_attr1(const float* __restrict__ x,
                                               const float* __restrict__ W1) {
    __shared__ float xs[10][IN_DIMS];  // 5KB
    __shared__ float ws[10][EMB];      // 2.5KB
    int t = threadIdx.x;
    int i0 = (t >> 4) * 8;   // 16 groups of 8 input-dims
    int e0 = (t & 15) * 4;   // 16 groups of 4 emb-dims
    float acc[8][4];
    #pragma unroll
    for (int a = 0; a < 8; a++)
        #pragma unroll
        for (int b = 0; b < 4; b++) acc[a][b] = 0.f;
    int rbase = blockIdx.x * 100;
    for (int c = 0; c < 10; c++) {
        for (int i = t; i < 10*IN_DIMS; i += 256) {
            int r = rbase + c*10 + i / IN_DIMS;
            xs[i / IN_DIMS][i % IN_DIMS] = x[(size_t)r*IN_DIMS + (i % IN_DIMS)];
        }
        for (int i = t; i < 10*EMB; i += 256) {
            int r = rbase + c*10 + i / EMB;
            ws[i / EMB][i % EMB] = W1[(size_t)r*EMB + (i % EMB)];
        }
        __syncthreads();
        #pragma unroll
        for (int rr = 0; rr < 10; rr++) {
            float wv[4];
            #pragma unroll
            for (int j = 0; j < 4; j++) wv[j] = ws[rr][e0 + j];
            #pragma unroll
            for (int ii = 0; ii < 8; ii++) {
                float xv = xs[rr][i0 + ii];
                #pragma unroll
                for (int j = 0; j < 4; j++) acc[ii][j] += xv * wv[j];
            }
        }
        __syncthreads();
    }
    #pragma unroll
    for (int ii = 0; ii < 8; ii++)
        #pragma unroll
        for (int j = 0; j < 4; j++)
            atomicAdd(&g_attr_part[(i0+ii)*EMB + e0 + j], acc[ii][j]);
}

// xa2 = relu(attr_part + b1) @ W_attr2 + b2    (single block)
__global__ __launch_bounds__(256) void k_attr2(const float* __restrict__ b1,
                                               const float* __restrict__ W2,
                                               const float* __restrict__ b2) {
    __shared__ float xa1[IN_DIMS*EMB];  // 32KB
    __shared__ float W2s[EMB*HID];      // 16KB
    int t = threadIdx.x;
    for (int i = t; i < IN_DIMS*EMB; i += 256)
        xa1[i] = fmaxf(g_attr_part[i] + b1[i % EMB], 0.f);
    for (int i = t; i < EMB*HID; i += 256) W2s[i] = W2[i];
    __syncthreads();
    int i0 = (t >> 4) * 8;
    int h0 = (t & 15) * 4;
    float acc[8][4];
    #pragma unroll
    for (int a = 0; a < 8; a++)
        #pragma unroll
        for (int b = 0; b < 4; b++) acc[a][b] = 0.f;
    for (int k = 0; k < EMB; k++) {
        float wv[4];
        #pragma unroll
        for (int j = 0; j < 4; j++) wv[j] = W2s[k*HID + h0 + j];
        #pragma unroll
        for (int ii = 0; ii < 8; ii++) {
            float xv = xa1[(i0+ii)*EMB + k];
            #pragma unroll
            for (int j = 0; j < 4; j++) acc[ii][j] += xv * wv[j];
        }
    }
    #pragma unroll
    for (int ii = 0; ii < 8; ii++)
        #pragma unroll
        for (int j = 0; j < 4; j++)
            g_xa2[(i0+ii)*HID + h0 + j] = acc[ii][j] + b2[h0 + j];
}

// x_ = embP @ xa2^T    [N,64]x[64,128] -> [N,128]
__global__ __launch_bounds__(256) void k_xout(float* __restrict__ out) {
    __shared__ float xa[IN_DIMS*(HID+1)];  // padded, ~33KB
    __shared__ float es[32*HID];           // 8KB
    int t = threadIdx.x;
    for (int i = t; i < IN_DIMS*HID; i += 256) {
        int r = i / HID, c = i % HID;
        xa[r*(HID+1) + c] = g_xa2[i];
    }
    int nb = blockIdx.x * 32;
    for (int i = t; i < 32*HID; i += 256) es[i] = g_embP[nb*HID + i];
    __syncthreads();
    int nl = t >> 3;
    int ib = (t & 7) * 16;
    const float* e = &es[nl*HID];
    int n = nb + nl;
    if (n >= N_NODES) return;
    for (int ii = 0; ii < 16; ii++) {
        int i = ib + ii;
        const float* w = &xa[i*(HID+1)];
        float acc = 0.f;
        #pragma unroll 8
        for (int k = 0; k < HID; k++) acc += e[k]*w[k];
        out[(size_t)n*IN_DIMS + i] = acc;
    }
}

// s_ = sigmoid(embP @ embP^T), symmetric: compute tj>=ti tile-pairs, mirror store
#define BK 32
__global__ __launch_bounds__(256) void k_s(float* __restrict__ sout) {
    __shared__ float As[BK][TILE+4];   // [32][132]
    __shared__ float Bs[BK][TILE+4];
    // block -> (ti, tj), tj >= ti
    int b = blockIdx.x;
    int ti = 0;
    {
        int rem = b, rowlen = NT;
        while (rem >= rowlen) { rem -= rowlen; ti++; rowlen--; }
        b = rem;
    }
    int tj = ti + b;
    int t = threadIdx.x;
    int ty = t >> 4, tx = t & 15;
    float c[8][8];
    #pragma unroll
    for (int i = 0; i < 8; i++)
        #pragma unroll
        for (int j = 0; j < 8; j++) c[i][j] = 0.f;

    const float* A = &g_embP[ti*TILE*HID];
    const float* B = &g_embP[tj*TILE*HID];

    for (int k0 = 0; k0 < HID; k0 += BK) {
        #pragma unroll
        for (int it = 0; it < 4; it++) {
            int f = t + it*256;           // 0..1023 float4 slots
            int row = f >> 3;             // 8 float4 per row of BK=32
            int col4 = (f & 7) * 4;
            float4 av = *(const float4*)&A[row*HID + k0 + col4];
            float4 bv = *(const float4*)&B[row*HID + k0 + col4];
            As[col4+0][row]=av.x; As[col4+1][row]=av.y; As[col4+2][row]=av.z; As[col4+3][row]=av.w;
            Bs[col4+0][row]=bv.x; Bs[col4+1][row]=bv.y; Bs[col4+2][row]=bv.z; Bs[col4+3][row]=bv.w;
        }
        __syncthreads();
        #pragma unroll
        for (int kk = 0; kk < BK; kk++) {
            float a[8], bb[8];
            *(float4*)&a[0]  = *(const float4*)&As[kk][ty*8];
            *(float4*)&a[4]  = *(const float4*)&As[kk][ty*8+4];
            *(float4*)&bb[0] = *(const float4*)&Bs[kk][tx*8];
            *(float4*)&bb[4] = *(const float4*)&Bs[kk][tx*8+4];
            #pragma unroll
            for (int i = 0; i < 8; i++)
                #pragma unroll
                for (int j = 0; j < 8; j++) c[i][j] += a[i]*bb[j];
        }
        __syncthreads();
    }
    // sigmoid
    #pragma unroll
    for (int i = 0; i < 8; i++)
        #pragma unroll
        for (int j = 0; j < 8; j++)
            c[i][j] = 1.f / (1.f + __expf(-c[i][j]));

    int gr0 = ti*TILE + ty*8;
    int gc0 = tj*TILE + tx*8;
    // normal tile
    #pragma unroll
    for (int i = 0; i < 8; i++) {
        int gr = gr0 + i;
        if (gr >= N_NODES) continue;
        size_t base = (size_t)gr * N_NODES + gc0;
        if (gc0 + 7 < N_NODES) {
            *(float4*)&sout[base]   = make_float4(c[i][0],c[i][1],c[i][2],c[i][3]);
            *(float4*)&sout[base+4] = make_float4(c[i][4],c[i][5],c[i][6],c[i][7]);
        } else {
            for (int j = 0; j < 8; j++)
                if (gc0 + j < N_NODES) sout[base + j] = c[i][j];
        }
    }
    // mirror tile (transposed)
    if (ti != tj) {
        #pragma unroll
        for (int j = 0; j < 8; j++) {
            int gc = gc0 + j;
            if (gc >= N_NODES) continue;
            size_t base = (size_t)gc * N_NODES + gr0;
            if (gr0 + 7 < N_NODES) {
                *(float4*)&sout[base]   = make_float4(c[0][j],c[1][j],c[2][j],c[3][j]);
                *(float4*)&sout[base+4] = make_float4(c[4][j],c[5][j],c[6][j],c[7][j]);
            } else {
                for (int i = 0; i < 8; i++)
                    if (gr0 + i < N_NODES) sout[base + i] = c[i][j];
            }
        }
    }
}

// ---------------- launch ----------------
extern "C" void kernel_launch(void* const* d_in, const int* in_sizes, int n_in,
                              void* d_out, int out_size) {
    const float* x       = (const float*)d_in[0];
    const int*   ei      = (const int*)d_in[1];
    // d_in[2] = batch_size (== N, unused)
    const float* W_stru  = (const float*)d_in[3];
    const float* b_stru  = (const float*)d_in[4];
    const float* W_gat   = (const float*)d_in[5];
    const float* att_src = (const float*)d_in[6];
    const float* att_dst = (const float*)d_in[7];
    const float* b_gat   = (const float*)d_in[8];
    const float* W_attr1 = (const float*)d_in[9];
    const float* b_attr1 = (const float*)d_in[10];
    const float* W_attr2 = (const float*)d_in[11];
    const float* b_attr2 = (const float*)d_in[12];

    int E = in_sizes[1] / 2;
    int EN = E + N_NODES;

    float* out   = (float*)d_out;
    float* x_out = out;                                  // [N, IN] first
    float* s_out = out + (size_t)N_NODES * IN_DIMS;      // [N, N] second

    k_zero  <<<148, 256>>>();
    k_stru  <<<(N_NODES + 15) / 16, 256>>>(x, W_stru, b_stru);
    k_gatlin<<<(N_NODES + 15) / 16, 256>>>(W_gat);
    k_att   <<<(N_NODES * 32 + 255) / 256, 256>>>(att_src, att_dst);
    k_emax  <<<(EN + 255) / 256, 256>>>(ei, E);
    k_eexp  <<<(EN + 255) / 256, 256>>>(ei, E);
    k_eaggr <<<((size_t)EN * 32 + 255) / 256, 256>>>(ei, E);
    k_femb  <<<(NPAD * HID + 255) / 256, 256>>>(b_gat);
    k_attr1 <<<100, 256>>>(x, W_attr1);
    k_attr2 <<<1, 256>>>(b_attr1, W_attr2, b_attr2);
    k_xout  <<<(N_NODES + 31) / 32, 256>>>(x_out);
    k_s     <<<NT * (NT + 1) / 2, 256>>>(s_out);
}

// round 2
// speedup vs baseline: 1.1870x; 1.1870x over previous
#include <cuda_runtime.h>
#include <cuda_bf16.h>
#include <math.h>
#include <stdint.h>

#define N_NODES 10000
#define IN_DIMS 128
#define EMB 64
#define HID 64
#define NEG_SLOPE 0.2f
#define TILE 128
#define NT 79                 // ceil(N/128)
#define NPAD (NT*TILE)        // 10112
#define MAXEDGE 400000
#define KSPLIT 192            // hi|lo|hi  /  hi|hi|lo

// ---------------- scratch (no allocations allowed) ----------------
__device__ float    g_h[N_NODES*EMB];
__device__ float    g_hp[N_NODES*HID];
__device__ float    g_asrc[N_NODES];
__device__ float    g_adst[N_NODES];
__device__ unsigned g_mord[N_NODES];
__device__ float    g_denom[N_NODES];
__device__ float    g_eval[MAXEDGE + N_NODES];
__device__ float    g_w[MAXEDGE + N_NODES];
__device__ float    g_emb_acc[N_NODES*HID];
__device__ float    g_embP[NPAD*HID];       // emb + b_gat, zero-padded
__device__ float    g_attr_part[IN_DIMS*EMB];
__device__ float    g_xa2[IN_DIMS*HID];
__device__ __align__(16) __nv_bfloat16 g_Abf[NPAD*KSPLIT];  // [hi|lo|hi]
__device__ __align__(16) __nv_bfloat16 g_Bbf[NPAD*KSPLIT];  // [hi|hi|lo]

// ---------------- helpers ----------------
__device__ __forceinline__ unsigned f2ord(float f) {
    unsigned b = __float_as_uint(f);
    return (b & 0x80000000u) ? ~b : (b | 0x80000000u);
}
__device__ __forceinline__ float ord2f(unsigned u) {
    unsigned b = (u & 0x80000000u) ? (u & 0x7fffffffu) : ~u;
    return __uint_as_float(b);
}

// ---------------- kernels ----------------
__global__ void k_zero() {
    int i = blockIdx.x * blockDim.x + threadIdx.x;
    int stride = gridDim.x * blockDim.x;
    for (int j = i; j < N_NODES*HID; j += stride) g_emb_acc[j] = 0.f;
    for (int j = i; j < N_NODES; j += stride) { g_mord[j] = 0u; g_denom[j] = 0.f; }
    for (int j = i; j < IN_DIMS*EMB; j += stride) g_attr_part[j] = 0.f;
}

// h = relu(x @ W_stru + b_stru)   [N,128]x[128,64]
__global__ __launch_bounds__(256) void k_stru(const float* __restrict__ x,
                                              const float* __restrict__ W,
                                              const float* __restrict__ b) {
    __shared__ float Ws[IN_DIMS*EMB];
    __shared__ float xs[16*IN_DIMS];
    int t = threadIdx.x;
    for (int i = t; i < IN_DIMS*EMB; i += 256) Ws[i] = W[i];
    int nbase = blockIdx.x * 16;
    for (int i = t; i < 16*IN_DIMS; i += 256) {
        int n = nbase + i / IN_DIMS;
        xs[i] = (n < N_NODES) ? x[(size_t)n*IN_DIMS + (i % IN_DIMS)] : 0.f;
    }
    __syncthreads();
    int nl = t >> 4;
    int e0 = (t & 15) * 4;
    float a0=0.f, a1=0.f, a2=0.f, a3=0.f;
    #pragma unroll 4
    for (int k = 0; k < IN_DIMS; k++) {
        float xv = xs[nl*IN_DIMS + k];
        const float* w = &Ws[k*EMB + e0];
        a0 += xv*w[0]; a1 += xv*w[1]; a2 += xv*w[2]; a3 += xv*w[3];
    }
    int n = nbase + nl;
    if (n < N_NODES) {
        float* o = &g_h[n*EMB + e0];
        o[0] = fmaxf(a0 + b[e0+0], 0.f);
        o[1] = fmaxf(a1 + b[e0+1], 0.f);
        o[2] = fmaxf(a2 + b[e0+2], 0.f);
        o[3] = fmaxf(a3 + b[e0+3], 0.f);
    }
}

// hp = h @ W_gat   [N,64]x[64,64]
__global__ __launch_bounds__(256) void k_gatlin(const float* __restrict__ W) {
    __shared__ float Ws[EMB*HID];
    __shared__ float hs[16*EMB];
    int t = threadIdx.x;
    for (int i = t; i < EMB*HID; i += 256) Ws[i] = W[i];
    int nbase = blockIdx.x * 16;
    for (int i = t; i < 16*EMB; i += 256) {
        int n = nbase + i / EMB;
        hs[i] = (n < N_NODES) ? g_h[n*EMB + (i % EMB)] : 0.f;
    }
    __syncthreads();
    int nl = t >> 4;
    int e0 = (t & 15) * 4;
    float a0=0.f, a1=0.f, a2=0.f, a3=0.f;
    #pragma unroll 8
    for (int k = 0; k < EMB; k++) {
        float xv = hs[nl*EMB + k];
        const float* w = &Ws[k*HID + e0];
        a0 += xv*w[0]; a1 += xv*w[1]; a2 += xv*w[2]; a3 += xv*w[3];
    }
    int n = nbase + nl;
    if (n < N_NODES) {
        float* o = &g_hp[n*HID + e0];
        o[0]=a0; o[1]=a1; o[2]=a2; o[3]=a3;
    }
}

__global__ void k_att(const float* __restrict__ att_s, const float* __restrict__ att_d) {
    int warp = (blockIdx.x * blockDim.x + threadIdx.x) >> 5;
    int lane = threadIdx.x & 31;
    if (warp >= N_NODES) return;
    float h0 = g_hp[warp*HID + lane];
    float h1 = g_hp[warp*HID + 32 + lane];
    float s = h0*att_s[lane] + h1*att_s[32+lane];
    float d = h0*att_d[lane] + h1*att_d[32+lane];
    #pragma unroll
    for (int o = 16; o; o >>= 1) {
        s += __shfl_xor_sync(0xffffffffu, s, o);
        d += __shfl_xor_sync(0xffffffffu, d, o);
    }
    if (lane == 0) { g_asrc[warp] = s; g_adst[warp] = d; }
}

__global__ void k_emax(const int* __restrict__ ei, int E) {
    int i = blockIdx.x * blockDim.x + threadIdx.x;
    if (i >= E + N_NODES) return;
    int s, d;
    if (i < E) { s = ei[i]; d = ei[E + i]; } else { s = d = i - E; }
    float e = g_asrc[s] + g_adst[d];
    e = (e > 0.f) ? e : NEG_SLOPE * e;
    g_eval[i] = e;
    atomicMax(&g_mord[d], f2ord(e));
}

__global__ void k_eexp(const int* __restrict__ ei, int E) {
    int i = blockIdx.x * blockDim.x + threadIdx.x;
    if (i >= E + N_NODES) return;
    int d = (i < E) ? ei[E + i] : (i - E);
    float m = ord2f(g_mord[d]);
    float w = __expf(g_eval[i] - m);
    g_w[i] = w;
    atomicAdd(&g_denom[d], w);
}

__global__ void k_eaggr(const int* __restrict__ ei, int E) {
    int warp = (blockIdx.x * blockDim.x + threadIdx.x) >> 5;
    int lane = threadIdx.x & 31;
    if (warp >= E + N_NODES) return;
    int s, d;
    if (warp < E) { s = ei[warp]; d = ei[E + warp]; } else { s = d = warp - E; }
    float coef = g_w[warp] / g_denom[d];
    atomicAdd(&g_emb_acc[d*HID + lane],      g_hp[s*HID + lane]      * coef);
    atomicAdd(&g_emb_acc[d*HID + 32 + lane], g_hp[s*HID + 32 + lane] * coef);
}

// embP = emb_acc + b_gat, plus bf16 hi/lo split matrices for the MMA GEMM
__global__ void k_femb(const float* __restrict__ bg) {
    int i = blockIdx.x * blockDim.x + threadIdx.x;
    if (i >= NPAD*HID) return;
    int n = i >> 6, j = i & 63;
    float v = (n < N_NODES) ? (g_emb_acc[i] + bg[j]) : 0.f;
    g_embP[i] = v;
    __nv_bfloat16 hi = __float2bfloat16(v);
    __nv_bfloat16 lo = __float2bfloat16(v - __bfloat162float(hi));
    size_t base = (size_t)n * KSPLIT + j;
    g_Abf[base]       = hi;
    g_Abf[base + 64]  = lo;
    g_Abf[base + 128] = hi;
    g_Bbf[base]       = hi;
    g_Bbf[base + 64]  = hi;
    g_Bbf[base + 128] = lo;
}

// attr_part = x^T @ W_attr1  (split over 100 blocks)
__global__ __launch_bounds__(256) void k_attr1(const float* __restrict__ x,
                                               const float* __restrict__ W1) {
    __shared__ float xs[10][IN_DIMS];
    __shared__ float ws[10][EMB];
    int t = threadIdx.x;
    int i0 = (t >> 4) * 8;
    int e0 = (t & 15) * 4;
    float acc[8][4];
    #pragma unroll
    for (int a = 0; a < 8; a++)
        #pragma unroll
        for (int b = 0; b < 4; b++) acc[a][b] = 0.f;
    int rbase = blockIdx.x * 100;
    for (int c = 0; c < 10; c++) {
        for (int i = t; i < 10*IN_DIMS; i += 256) {
            int r = rbase + c*10 + i / IN_DIMS;
            xs[i / IN_DIMS][i % IN_DIMS] = x[(size_t)r*IN_DIMS + (i % IN_DIMS)];
        }
        for (int i = t; i < 10*EMB; i += 256) {
            int r = rbase + c*10 + i / EMB;
            ws[i / EMB][i % EMB] = W1[(size_t)r*EMB + (i % EMB)];
        }
        __syncthreads();
        #pragma unroll
        for (int rr = 0; rr < 10; rr++) {
            float wv[4];
            #pragma unroll
            for (int j = 0; j < 4; j++) wv[j] = ws[rr][e0 + j];
            #pragma unroll
            for (int ii = 0; ii < 8; ii++) {
                float xv = xs[rr][i0 + ii];
                #pragma unroll
                for (int j = 0; j < 4; j++) acc[ii][j] += xv * wv[j];
            }
        }
        __syncthreads();
    }
    #pragma unroll
    for (int ii = 0; ii < 8; ii++)
        #pragma unroll
        for (int j = 0; j < 4; j++)
            atomicAdd(&g_attr_part[(i0+ii)*EMB + e0 + j], acc[ii][j]);
}

__global__ __launch_bounds__(256) void k_attr2(const float* __restrict__ b1,
                                               const float* __restrict__ W2,
                                               const float* __restrict__ b2) {
    __shared__ float xa1[IN_DIMS*EMB];
    __shared__ float W2s[EMB*HID];
    int t = threadIdx.x;
    for (int i = t; i < IN_DIMS*EMB; i += 256)
        xa1[i] = fmaxf(g_attr_part[i] + b1[i % EMB], 0.f);
    for (int i = t; i < EMB*HID; i += 256) W2s[i] = W2[i];
    __syncthreads();
    int i0 = (t >> 4) * 8;
    int h0 = (t & 15) * 4;
    float acc[8][4];
    #pragma unroll
    for (int a = 0; a < 8; a++)
        #pragma unroll
        for (int b = 0; b < 4; b++) acc[a][b] = 0.f;
    for (int k = 0; k < EMB; k++) {
        float wv[4];
        #pragma unroll
        for (int j = 0; j < 4; j++) wv[j] = W2s[k*HID + h0 + j];
        #pragma unroll
        for (int ii = 0; ii < 8; ii++) {
            float xv = xa1[(i0+ii)*EMB + k];
            #pragma unroll
            for (int j = 0; j < 4; j++) acc[ii][j] += xv * wv[j];
        }
    }
    #pragma unroll
    for (int ii = 0; ii < 8; ii++)
        #pragma unroll
        for (int j = 0; j < 4; j++)
            g_xa2[(i0+ii)*HID + h0 + j] = acc[ii][j] + b2[h0 + j];
}

// x_ = embP @ xa2^T    [N,64]x[64,128] -> [N,128]
__global__ __launch_bounds__(256) void k_xout(float* __restrict__ out) {
    __shared__ float xa[IN_DIMS*(HID+1)];
    __shared__ float es[32*HID];
    int t = threadIdx.x;
    for (int i = t; i < IN_DIMS*HID; i += 256) {
        int r = i / HID, c = i % HID;
        xa[r*(HID+1) + c] = g_xa2[i];
    }
    int nb = blockIdx.x * 32;
    for (int i = t; i < 32*HID; i += 256) es[i] = g_embP[nb*HID + i];
    __syncthreads();
    int nl = t >> 3;
    int ib = (t & 7) * 16;
    const float* e = &es[nl*HID];
    int n = nb + nl;
    if (n >= N_NODES) return;
    for (int ii = 0; ii < 16; ii++) {
        int i = ib + ii;
        const float* w = &xa[i*(HID+1)];
        float acc = 0.f;
        #pragma unroll 8
        for (int k = 0; k < HID; k++) acc += e[k]*w[k];
        out[(size_t)n*IN_DIMS + i] = acc;
    }
}

// ---------------- tensor-core s_ GEMM ----------------
// s_ = sigmoid(A' @ B'^T) where A'=[hi|lo|hi], B'=[hi|hi|lo] (K=192 bf16,
// fp32 accumulate) ==> hi*hi + lo*hi + hi*lo ~= fp32 product to ~2^-16.
// Symmetric: blocks cover upper tile-triangle, mirror-store the transpose.
#define SPAD 24   // smem row stride in bf16 (conflict-free fragment loads)

__device__ __forceinline__ void mma16816(float c[4], uint32_t a0, uint32_t a1,
                                         uint32_t a2, uint32_t a3,
                                         uint32_t b0, uint32_t b1) {
    asm volatile(
        "mma.sync.aligned.m16n8k16.row.col.f32.bf16.bf16.f32 "
        "{%0,%1,%2,%3}, {%4,%5,%6,%7}, {%8,%9}, {%0,%1,%2,%3};"
        : "+f"(c[0]), "+f"(c[1]), "+f"(c[2]), "+f"(c[3])
        : "r"(a0), "r"(a1), "r"(a2), "r"(a3), "r"(b0), "r"(b1));
}

__global__ __launch_bounds__(256) void k_s_mma(float* __restrict__ sout) {
    __shared__ __align__(16) __nv_bfloat16 As[TILE][SPAD];
    __shared__ __align__(16) __nv_bfloat16 Bs[TILE][SPAD];

    // block -> (ti, tj), tj >= ti
    int b = blockIdx.x;
    int ti = 0;
    {
        int rem = b, rowlen = NT;
        while (rem >= rowlen) { rem -= rowlen; ti++; rowlen--; }
        b = rem;
    }
    int tj = ti + b;

    int t = threadIdx.x;
    int warp = t >> 5, lane = t & 31;
    int wm = warp >> 1, wn = warp & 1;       // 4x2 warps: warp tile 32x64
    int g = lane >> 2, tq = lane & 3;

    int ldrow = t >> 1;          // 0..127
    int ldpart = (t & 1) * 8;    // 0 or 8 (bf16 elems)

    const __nv_bfloat16* gA = &g_Abf[((size_t)ti*TILE + ldrow)*KSPLIT + ldpart];
    const __nv_bfloat16* gB = &g_Bbf[((size_t)tj*TILE + ldrow)*KSPLIT + ldpart];

    float c[2][8][4];
    #pragma unroll
    for (int mt = 0; mt < 2; mt++)
        #pragma unroll
        for (int nt = 0; nt < 8; nt++)
            #pragma unroll
            for (int r = 0; r < 4; r++) c[mt][nt][r] = 0.f;

    for (int ks = 0; ks < KSPLIT/16; ks++) {
        *(float4*)&As[ldrow][ldpart] = *(const float4*)(gA + ks*16);
        *(float4*)&Bs[ldrow][ldpart] = *(const float4*)(gB + ks*16);
        __syncthreads();

        uint32_t a[2][4];
        #pragma unroll
        for (int mt = 0; mt < 2; mt++) {
            int ar = wm*32 + mt*16 + g;
            a[mt][0] = *(const uint32_t*)&As[ar][tq*2];
            a[mt][1] = *(const uint32_t*)&As[ar+8][tq*2];
            a[mt][2] = *(const uint32_t*)&As[ar][tq*2+8];
            a[mt][3] = *(const uint32_t*)&As[ar+8][tq*2+8];
        }
        #pragma unroll
        for (int nt = 0; nt < 8; nt++) {
            int br = wn*64 + nt*8 + g;
            uint32_t b0 = *(const uint32_t*)&Bs[br][tq*2];
            uint32_t b1 = *(const uint32_t*)&Bs[br][tq*2+8];
            mma16816(c[0][nt], a[0][0], a[0][1], a[0][2], a[0][3], b0, b1);
            mma16816(c[1][nt], a[1][0], a[1][1], a[1][2], a[1][3], b0, b1);
        }
        __syncthreads();
    }

    // sigmoid in-place
    #pragma unroll
    for (int mt = 0; mt < 2; mt++)
        #pragma unroll
        for (int nt = 0; nt < 8; nt++)
            #pragma unroll
            for (int r = 0; r < 4; r++)
                c[mt][nt][r] = 1.f / (1.f + __expf(-c[mt][nt][r]));

    bool diag = (ti == tj);
    #pragma unroll
    for (int mt = 0; mt < 2; mt++) {
        #pragma unroll
        for (int rr = 0; rr < 2; rr++) {
            int gr = ti*TILE + wm*32 + mt*16 + g + rr*8;
            bool rok = gr < N_NODES;
            size_t obase = (size_t)gr * N_NODES;
            #pragma unroll
            for (int nt = 0; nt < 8; nt++) {
                int gc = tj*TILE + wn*64 + nt*8 + tq*2;
                float v0 = c[mt][nt][rr*2 + 0];
                float v1 = c[mt][nt][rr*2 + 1];
                if (rok && gc < N_NODES)
                    *(float2*)&sout[obase + gc] = make_float2(v0, v1);
                if (!diag && rok && gc < N_NODES) {
                    sout[(size_t)gc * N_NODES + gr]       = v0;
                    sout[(size_t)(gc+1) * N_NODES + gr]   = v1;
                }
            }
        }
    }
}

// ---------------- launch ----------------
extern "C" void kernel_launch(void* const* d_in, const int* in_sizes, int n_in,
                              void* d_out, int out_size) {
    const float* x       = (const float*)d_in[0];
    const int*   ei      = (const int*)d_in[1];
    const float* W_stru  = (const float*)d_in[3];
    const float* b_stru  = (const float*)d_in[4];
    const float* W_gat   = (const float*)d_in[5];
    const float* att_src = (const float*)d_in[6];
    const float* att_dst = (const float*)d_in[7];
    const float* b_gat   = (const float*)d_in[8];
    const float* W_attr1 = (const float*)d_in[9];
    const float* b_attr1 = (const float*)d_in[10];
    const float* W_attr2 = (const float*)d_in[11];
    const float* b_attr2 = (const float*)d_in[12];

    int E = in_sizes[1] / 2;
    int EN = E + N_NODES;

    float* out   = (float*)d_out;
    float* x_out = out;
    float* s_out = out + (size_t)N_NODES * IN_DIMS;

    k_zero  <<<148, 256>>>();
    k_stru  <<<(N_NODES + 15) / 16, 256>>>(x, W_stru, b_stru);
    k_gatlin<<<(N_NODES + 15) / 16, 256>>>(W_gat);
    k_att   <<<(N_NODES * 32 + 255) / 256, 256>>>(att_src, att_dst);
    k_emax  <<<(EN + 255) / 256, 256>>>(ei, E);
    k_eexp  <<<(EN + 255) / 256, 256>>>(ei, E);
    k_eaggr <<<((size_t)EN * 32 + 255) / 256, 256>>>(ei, E);
    k_femb  <<<(NPAD * HID + 255) / 256, 256>>>(b_gat);
    k_attr1 <<<100, 256>>>(x, W_attr1);
    k_attr2 <<<1, 256>>>(b_attr1, W_attr2, b_attr2);
    k_xout  <<<(N_NODES + 31) / 32, 256>>>(x_out);
    k_s_mma <<<NT * (NT + 1) / 2, 256>>>(s_out);
}